// round 1
// baseline (speedup 1.0000x reference)
#include <cuda_runtime.h>

#define NB 2
#define NT 2048
#define NE 1024
#define NH 16
#define NZ 64

// Scratch (allocation-free rule: __device__ globals)
__device__ float g_Q[NB*NH*NT*NZ];     // [bh][t][z]
__device__ float g_K[NB*NH*NT*NZ];     // [bh][t][z]
__device__ float g_invn[NH*NZ];

// ---------------------------------------------------------------------------
// invn[h,z] = 1 / ||wq[h, :, z]||_2   (norm over e axis)
// ---------------------------------------------------------------------------
__global__ void norm_kernel(const float* __restrict__ wq) {
    int h = blockIdx.x;          // 16
    int z = threadIdx.x;         // 64 -> coalesced over z
    const float* p = wq + (size_t)h*NE*NZ + z;
    float s = 0.f;
#pragma unroll 8
    for (int e = 0; e < NE; ++e) {
        float v = p[(size_t)e*NZ];
        s = fmaf(v, v, s);
    }
    g_invn[h*NZ + z] = rsqrtf(s);
}

// ---------------------------------------------------------------------------
// C[bh][t][z] = (sum_e G[b][t][e] * W[h][e][z]) * invn[h][z]
// Tile: 256(t) x 64(z), TK=16, 256 threads, 8x8 micro-tile per thread.
// ---------------------------------------------------------------------------
__global__ __launch_bounds__(256) void proj_kernel(
    const float* __restrict__ G, const float* __restrict__ W, int which)
{
    __shared__ float As[16][260];   // A^T: As[k][m], pad 260 (16B-aligned rows)
    __shared__ float Bs[16][64];    // B:   Bs[k][n]
    float* C = which ? g_K : g_Q;
    int bh = blockIdx.y;
    int b = bh / NH, h = bh % NH;
    int t0 = blockIdx.x * 256;
    int tid = threadIdx.x;
    int tx = tid & 7;               // n: cols tx*8 .. +7  (8*8 = 64)
    int ty = tid >> 3;              // m: rows ty*8 .. +7  (32*8 = 256)
    const float* Gp = G + (size_t)b*NT*NE + (size_t)t0*NE;
    const float* Wp = W + (size_t)h*NE*NZ;

    float acc[8][8];
#pragma unroll
    for (int i = 0; i < 8; ++i)
#pragma unroll
        for (int j = 0; j < 8; ++j) acc[i][j] = 0.f;

    for (int e0 = 0; e0 < NE; e0 += 16) {
        // Load A tile 256x16 (coalesced 16-float runs), store transposed
#pragma unroll
        for (int i = 0; i < 16; ++i) {
            int j = tid + i*256;
            int r = j >> 4, c = j & 15;
            As[c][r] = Gp[(size_t)r*NE + e0 + c];
        }
        // Load B tile 16x64 (fully coalesced rows)
#pragma unroll
        for (int i = 0; i < 4; ++i) {
            int j = tid + i*256;
            int r = j >> 6, c = j & 63;
            Bs[r][c] = Wp[(size_t)(e0 + r)*NZ + c];
        }
        __syncthreads();
#pragma unroll 8
        for (int k = 0; k < 16; ++k) {
            float4 a0 = *(const float4*)&As[k][ty*8];
            float4 a1 = *(const float4*)&As[k][ty*8+4];
            float4 b0 = *(const float4*)&Bs[k][tx*8];
            float4 b1 = *(const float4*)&Bs[k][tx*8+4];
            float av[8] = {a0.x,a0.y,a0.z,a0.w,a1.x,a1.y,a1.z,a1.w};
            float bv[8] = {b0.x,b0.y,b0.z,b0.w,b1.x,b1.y,b1.z,b1.w};
#pragma unroll
            for (int i = 0; i < 8; ++i)
#pragma unroll
                for (int j = 0; j < 8; ++j)
                    acc[i][j] = fmaf(av[i], bv[j], acc[i][j]);
        }
        __syncthreads();
    }

    float sc[8];
#pragma unroll
    for (int j = 0; j < 8; ++j) sc[j] = g_invn[h*NZ + tx*8 + j];
    float* Cp = C + (size_t)bh*NT*NZ + (size_t)t0*NZ;
#pragma unroll
    for (int i = 0; i < 8; ++i) {
        int row = ty*8 + i;
        float4 o0, o1;
        o0.x = acc[i][0]*sc[0]; o0.y = acc[i][1]*sc[1];
        o0.z = acc[i][2]*sc[2]; o0.w = acc[i][3]*sc[3];
        o1.x = acc[i][4]*sc[4]; o1.y = acc[i][5]*sc[5];
        o1.z = acc[i][6]*sc[6]; o1.w = acc[i][7]*sc[7];
        *(float4*)&Cp[(size_t)row*NZ + tx*8]     = o0;
        *(float4*)&Cp[(size_t)row*NZ + tx*8 + 4] = o1;
    }
}

// ---------------------------------------------------------------------------
// Fast exp: exp(x) = 2^(x*log2e), degree-5 poly on f in [-0.5,0.5],
// scale by 2^n via exponent-bit splice. Rel err ~3e-6. No MUFU (EX2 rt=8
// would cost ~1.2ms for the 134M exps; this stays on the FMA pipe).
// ---------------------------------------------------------------------------
__device__ __forceinline__ float fexp(float x) {
    float y = x * 1.4426950408889634f;
    float t = y + 12582912.0f;                      // round-to-nearest-int trick
    int   n = __float_as_int(t) - 0x4B400000;
    float f = y - (t - 12582912.0f);                // f in [-0.5, 0.5]
    float p = 1.3333558146428443e-3f;
    p = fmaf(p, f, 9.6181291976353544e-3f);
    p = fmaf(p, f, 5.5504108664821580e-2f);
    p = fmaf(p, f, 2.4022650695910071e-1f);
    p = fmaf(p, f, 6.9314718055994531e-1f);
    p = fmaf(p, f, 1.0f);
    return p * __int_as_float((n + 127) << 23);
}

// ---------------------------------------------------------------------------
// out[bh][t] = log( sum_{s != t} exp( q[t].k[s] / 8 ) )
// Tile: 128(t) x 128(s), z=64 resident, 256 threads, 8x8 per thread.
// Q^T/K^T in dynamic smem, stride 132 (16B-aligned, conflict-free f4 reads).
// ---------------------------------------------------------------------------
__global__ __launch_bounds__(256) void attn_kernel(float* __restrict__ out)
{
    extern __shared__ float sm[];
    float* QsT = sm;                 // [64][132]
    float* KsT = sm + 64*132;        // [64][132]
    int bh = blockIdx.y;
    int t0 = blockIdx.x * 128;
    int tid = threadIdx.x;
    int tx = tid & 15;               // s group: cols tx*8 (16*8 = 128)
    int ty = tid >> 4;               // t group: rows ty*8 (16*8 = 128)
    const float* Qp = g_Q + (size_t)bh*NT*NZ;
    const float* Kp = g_K + (size_t)bh*NT*NZ;

    // Load Q tile once, transposed: QsT[z][trow]
#pragma unroll
    for (int i = 0; i < 32; ++i) {
        int j = tid + i*256;
        int r = j >> 6, c = j & 63;
        QsT[c*132 + r] = Qp[(size_t)(t0 + r)*NZ + c];
    }

    float accs[8];
#pragma unroll
    for (int i = 0; i < 8; ++i) accs[i] = 0.f;

    for (int st = 0; st < NT/128; ++st) {
        __syncthreads();             // guards KsT overwrite + first-iter Q load
        int s0 = st*128;
#pragma unroll
        for (int i = 0; i < 32; ++i) {
            int j = tid + i*256;
            int r = j >> 6, c = j & 63;
            KsT[c*132 + r] = Kp[(size_t)(s0 + r)*NZ + c];
        }
        __syncthreads();

        float sv[8][8];
#pragma unroll
        for (int i = 0; i < 8; ++i)
#pragma unroll
            for (int j = 0; j < 8; ++j) sv[i][j] = 0.f;

#pragma unroll 8
        for (int z = 0; z < 64; ++z) {
            float4 a0 = *(const float4*)&QsT[z*132 + ty*8];
            float4 a1 = *(const float4*)&QsT[z*132 + ty*8 + 4];
            float4 b0 = *(const float4*)&KsT[z*132 + tx*8];
            float4 b1 = *(const float4*)&KsT[z*132 + tx*8 + 4];
            float av[8] = {a0.x,a0.y,a0.z,a0.w,a1.x,a1.y,a1.z,a1.w};
            float bv[8] = {b0.x,b0.y,b0.z,b0.w,b1.x,b1.y,b1.z,b1.w};
#pragma unroll
            for (int i = 0; i < 8; ++i)
#pragma unroll
                for (int j = 0; j < 8; ++j)
                    sv[i][j] = fmaf(av[i], bv[j], sv[i][j]);
        }

        // scale 1/sqrt(64), exp, mask diagonal, accumulate
#pragma unroll
        for (int i = 0; i < 8; ++i) {
            int trow = t0 + ty*8 + i;
#pragma unroll
            for (int j = 0; j < 8; ++j) {
                int scol = s0 + tx*8 + j;
                float e = fexp(sv[i][j] * 0.125f);
                accs[i] += (trow == scol) ? 0.f : e;
            }
        }
    }

    // Reduce over the 16 s-lanes sharing each ty (lanes ty*16 .. ty*16+15,
    // always within one warp since 16 | 32).
#pragma unroll
    for (int i = 0; i < 8; ++i) {
        float v = accs[i];
        v += __shfl_xor_sync(0xffffffffu, v, 1);
        v += __shfl_xor_sync(0xffffffffu, v, 2);
        v += __shfl_xor_sync(0xffffffffu, v, 4);
        v += __shfl_xor_sync(0xffffffffu, v, 8);
        accs[i] = v;
    }
    if (tx == 0) {
#pragma unroll
        for (int i = 0; i < 8; ++i)
            out[(size_t)bh*NT + t0 + ty*8 + i] = logf(accs[i]);
    }
}

// ---------------------------------------------------------------------------
extern "C" void kernel_launch(void* const* d_in, const int* in_sizes, int n_in,
                              void* d_out, int out_size) {
    const float* gq = (const float*)d_in[0];
    const float* gk = (const float*)d_in[1];
    const float* wq = (const float*)d_in[2];
    const float* wk = (const float*)d_in[3];
    float* out = (float*)d_out;

    norm_kernel<<<NH, NZ>>>(wq);
    proj_kernel<<<dim3(NT/256, NB*NH), 256>>>(gq, wq, 0);
    proj_kernel<<<dim3(NT/256, NB*NH), 256>>>(gk, wk, 1);

    static const int attn_smem = 2 * 64 * 132 * (int)sizeof(float);  // 67584 B
    cudaFuncSetAttribute(attn_kernel,
                         cudaFuncAttributeMaxDynamicSharedMemorySize, attn_smem);
    attn_kernel<<<dim3(NT/128, NB*NH), 256, attn_smem>>>(out);
}

// round 3
// speedup vs baseline: 4.2149x; 4.2149x over previous
#include <cuda_runtime.h>
#include <cuda_bf16.h>
#include <cstdint>

#define NB 2
#define NT 2048
#define NE 1024
#define NH 16
#define NZ 64

// ---------------------------------------------------------------------------
// Scratch (__device__ globals; allocation-free rule)
// ---------------------------------------------------------------------------
__device__ __nv_bfloat16 g_Gq[NB*NT*NE];        // [b][t][e] bf16
__device__ __nv_bfloat16 g_Gk[NB*NT*NE];
__device__ __nv_bfloat16 g_Wq[NH*NZ*NE];        // W^T: [h][z][e] bf16, scaled by invn
__device__ __nv_bfloat16 g_Wk[NH*NZ*NE];
__device__ __nv_bfloat16 g_Q[NB*NH*NT*NZ];      // [bh][t][z] bf16
__device__ __nv_bfloat16 g_K[NB*NH*NT*NZ];
__device__ float g_invn[NH*NZ];

// ---------------------------------------------------------------------------
// Helpers
// ---------------------------------------------------------------------------
__device__ __forceinline__ uint32_t smem_u32(const void* p) {
    uint32_t a;
    asm("{ .reg .u64 t; cvta.to.shared.u64 t, %1; cvt.u32.u64 %0, t; }"
        : "=r"(a) : "l"(p));
    return a;
}

// 128B-row swizzle (Swizzle<3,4,3>): conflict-free ldmatrix + stores
#define SW128(o) ((o) ^ (((o) >> 3) & 0x70))

__device__ __forceinline__ void ldsm4(uint32_t* r, uint32_t addr) {
    asm volatile("ldmatrix.sync.aligned.m8n8.x4.shared.b16 {%0,%1,%2,%3}, [%4];"
        : "=r"(r[0]), "=r"(r[1]), "=r"(r[2]), "=r"(r[3]) : "r"(addr));
}
__device__ __forceinline__ void mma_bf16(float* c, const uint32_t* a, const uint32_t* b) {
    asm volatile("mma.sync.aligned.m16n8k16.row.col.f32.bf16.bf16.f32 "
        "{%0,%1,%2,%3}, {%4,%5,%6,%7}, {%8,%9}, {%0,%1,%2,%3};"
        : "+f"(c[0]), "+f"(c[1]), "+f"(c[2]), "+f"(c[3])
        : "r"(a[0]), "r"(a[1]), "r"(a[2]), "r"(a[3]), "r"(b[0]), "r"(b[1]));
}
// A-fragment ldmatrix address (row-major A, 128B rows): m16 x k16 tile
__device__ __forceinline__ uint32_t lda_addr(uint32_t base, int m0, int k0, int lane) {
    int row = m0 + (lane & 15);
    int col = k0 + (lane >> 4) * 8;
    return base + SW128(row * 128 + col * 2);
}
// B-fragment ldmatrix address (B^T stored [n][k], 128B rows): covers 2 n-atoms x k16
__device__ __forceinline__ uint32_t ldb_addr(uint32_t base, int n0, int k0, int lane) {
    int row = n0 + (lane & 7) + ((lane >> 4) << 3);
    int col = k0 + ((lane >> 3) & 1) * 8;
    return base + SW128(row * 128 + col * 2);
}

#define CPA16(dst, src) asm volatile("cp.async.cg.shared.global [%0], [%1], 16;" :: "r"(dst), "l"(src))
#define CPA_COMMIT()    asm volatile("cp.async.commit_group;" ::: "memory")
#define CPA_WAIT0()     asm volatile("cp.async.wait_group 0;" ::: "memory")
#define CPA_WAIT1()     asm volatile("cp.async.wait_group 1;" ::: "memory")

__device__ __forceinline__ float fex2(float x) {
    float r; asm("ex2.approx.ftz.f32 %0, %1;" : "=f"(r) : "f"(x)); return r;
}

// ---------------------------------------------------------------------------
// invn[h,z] = 1 / ||wq[h,:,z]||
// ---------------------------------------------------------------------------
__global__ void norm_kernel(const float* __restrict__ wq) {
    __shared__ float red[256];
    int h = blockIdx.x;
    int z = threadIdx.x & 63, part = threadIdx.x >> 6;
    const float* p = wq + (size_t)h*NE*NZ + (size_t)part*256*NZ + z;
    float s = 0.f;
#pragma unroll 8
    for (int e = 0; e < 256; ++e) { float v = p[(size_t)e*NZ]; s = fmaf(v, v, s); }
    red[threadIdx.x] = s;
    __syncthreads();
    if (part == 0) {
        s = red[z] + red[z+64] + red[z+128] + red[z+192];
        g_invn[h*NZ + z] = rsqrtf(s);
    }
}

// ---------------------------------------------------------------------------
// fp32 -> bf16 convert (vectorized)
// ---------------------------------------------------------------------------
__global__ void conv_g_kernel(const float* __restrict__ src,
                              __nv_bfloat16* __restrict__ dst, int n4) {
    int i = blockIdx.x * blockDim.x + threadIdx.x;
    if (i >= n4) return;
    float4 v = ((const float4*)src)[i];
    ((__nv_bfloat162*)dst)[2*i]   = __floats2bfloat162_rn(v.x, v.y);
    ((__nv_bfloat162*)dst)[2*i+1] = __floats2bfloat162_rn(v.z, v.w);
}

// ---------------------------------------------------------------------------
// wq,wk [h,e,z] fp32 -> W^T [h,z,e] bf16, both scaled by invn(h,z)
// ---------------------------------------------------------------------------
__global__ void conv_w_kernel(const float* __restrict__ wq, const float* __restrict__ wk) {
    int h = blockIdx.x;
    int z = threadIdx.x & 63, eg = threadIdx.x >> 6;
    float inv = g_invn[h*NZ + z];
    const float* pq = wq + (size_t)h*NE*NZ + z;
    const float* pk = wk + (size_t)h*NE*NZ + z;
    __nv_bfloat16* oq = g_Wq + (size_t)h*NZ*NE + (size_t)z*NE;
    __nv_bfloat16* ok = g_Wk + (size_t)h*NZ*NE + (size_t)z*NE;
    int e0 = eg * 256;
#pragma unroll 4
    for (int e = e0; e < e0 + 256; ++e) {
        oq[e] = __float2bfloat16(pq[(size_t)e*NZ] * inv);
        ok[e] = __float2bfloat16(pk[(size_t)e*NZ] * inv);
    }
}

// ---------------------------------------------------------------------------
// Projection: Out[bh][t][z] = G[b] @ W^T[h]   (CTA tile 128 x 64, K=1024)
// 256 threads / 8 warps (4m x 2n), warp tile 32x32.
// cp.async 2-stage pipeline; smem SW128-swizzled; mma.sync bf16.
// ---------------------------------------------------------------------------
__global__ __launch_bounds__(256) void proj_mma_kernel(
    const __nv_bfloat16* __restrict__ G,
    const __nv_bfloat16* __restrict__ W,
    __nv_bfloat16* __restrict__ Out)
{
    extern __shared__ char sm[];
    // layout: sA[2][128*64] (2x16KB), sB[2][64*64] (2x8KB)
    uint32_t sA_u = smem_u32(sm);
    uint32_t sB_u = sA_u + 2*16384;

    int tid = threadIdx.x, lane = tid & 31, w = tid >> 5;
    int wm = w & 3, wn = w >> 2;
    int bh = blockIdx.y, b = bh >> 4, h = bh & 15;
    int t0 = blockIdx.x * 128;

    const __nv_bfloat16* Gp = G + ((size_t)b*NT + t0) * NE;
    const __nv_bfloat16* Wp = W + (size_t)h*NZ*NE;

    // issue chunk c loads into buffer buf
    auto issue = [&](int c, int buf) {
        int e0 = c * 64;
#pragma unroll
        for (int i = 0; i < 4; ++i) {               // A: 128 rows x 128B
            int idx = tid + i*256;
            int r = idx >> 3, q = idx & 7;
            CPA16(sA_u + buf*16384 + SW128(r*128 + q*16),
                  Gp + (size_t)r*NE + e0 + q*8);
        }
#pragma unroll
        for (int i = 0; i < 2; ++i) {               // B: 64 rows x 128B
            int idx = tid + i*256;
            int r = idx >> 3, q = idx & 7;
            CPA16(sB_u + buf*8192 + SW128(r*128 + q*16),
                  Wp + (size_t)r*NE + e0 + q*8);
        }
        CPA_COMMIT();
    };

    float acc[2][4][4];
#pragma unroll
    for (int mi = 0; mi < 2; ++mi)
#pragma unroll
        for (int ni = 0; ni < 4; ++ni)
#pragma unroll
            for (int c = 0; c < 4; ++c) acc[mi][ni][c] = 0.f;

    issue(0, 0);
    for (int c = 0; c < 16; ++c) {
        int buf = c & 1;
        if (c + 1 < 16) { issue(c + 1, buf ^ 1); CPA_WAIT1(); }
        else CPA_WAIT0();
        __syncthreads();
        uint32_t bA = sA_u + buf*16384;
        uint32_t bB = sB_u + buf*8192;
#pragma unroll
        for (int ks = 0; ks < 4; ++ks) {
            uint32_t af0[4], af1[4], bf0[4], bf1[4];
            ldsm4(af0, lda_addr(bA, wm*32,      ks*16, lane));
            ldsm4(af1, lda_addr(bA, wm*32 + 16, ks*16, lane));
            ldsm4(bf0, ldb_addr(bB, wn*32,      ks*16, lane));
            ldsm4(bf1, ldb_addr(bB, wn*32 + 16, ks*16, lane));
            mma_bf16(acc[0][0], af0, bf0);
            mma_bf16(acc[0][1], af0, bf0 + 2);
            mma_bf16(acc[0][2], af0, bf1);
            mma_bf16(acc[0][3], af0, bf1 + 2);
            mma_bf16(acc[1][0], af1, bf0);
            mma_bf16(acc[1][1], af1, bf0 + 2);
            mma_bf16(acc[1][2], af1, bf1);
            mma_bf16(acc[1][3], af1, bf1 + 2);
        }
        __syncthreads();
    }

    // Epilogue: write bf16 [bh][t][z]
    __nv_bfloat16* Ob = Out + (size_t)bh*NT*NZ;
#pragma unroll
    for (int mi = 0; mi < 2; ++mi) {
        int row = t0 + wm*32 + mi*16 + (lane >> 2);
#pragma unroll
        for (int ni = 0; ni < 4; ++ni) {
            int col = wn*32 + ni*8 + 2*(lane & 3);
            *(__nv_bfloat162*)(Ob + (size_t)row*NZ + col) =
                __floats2bfloat162_rn(acc[mi][ni][0], acc[mi][ni][1]);
            *(__nv_bfloat162*)(Ob + (size_t)(row + 8)*NZ + col) =
                __floats2bfloat162_rn(acc[mi][ni][2], acc[mi][ni][3]);
        }
    }
}

// ---------------------------------------------------------------------------
// Attention: out[bh][t] = log(sum_{s!=t} exp(q[t].k[s]/8))
// CTA: 128 t-rows; 16 s-tiles of 128. 256 threads / 8 warps (4m x 2n),
// warp tile 32(t) x 64(s). Q fragments register-resident; K double-buffered.
// ---------------------------------------------------------------------------
__global__ __launch_bounds__(256) void attn_mma_kernel(float* __restrict__ out)
{
    extern __shared__ char sm[];
    uint32_t sQ_u = smem_u32(sm);                  // 16 KB
    uint32_t sK_u = sQ_u + 16384;                  // 2 x 16 KB
    float* red = (float*)(sm + 16384 + 32768);     // 256 floats

    int tid = threadIdx.x, lane = tid & 31, w = tid >> 5;
    int wm = w & 3, wn = w >> 2;
    int bh = blockIdx.y, mt = blockIdx.x;
    int t0 = mt * 128;

    const __nv_bfloat16* Qp = g_Q + (size_t)bh*NT*NZ;
    const __nv_bfloat16* Kp = g_K + (size_t)bh*NT*NZ;

    // Q tile (cp.async) + first K tile
#pragma unroll
    for (int i = 0; i < 4; ++i) {
        int idx = tid + i*256;
        int r = idx >> 3, q = idx & 7;
        CPA16(sQ_u + SW128(r*128 + q*16), Qp + (size_t)(t0 + r)*NZ + q*8);
    }
    auto issueK = [&](int st, int buf) {
        int s0 = st * 128;
#pragma unroll
        for (int i = 0; i < 4; ++i) {
            int idx = tid + i*256;
            int r = idx >> 3, q = idx & 7;
            CPA16(sK_u + buf*16384 + SW128(r*128 + q*16),
                  Kp + (size_t)(s0 + r)*NZ + q*8);
        }
        CPA_COMMIT();
    };
    issueK(0, 0);           // one group containing Q + K0
    CPA_WAIT0();
    __syncthreads();

    // Preload Q fragments: 2 m-atoms x 4 ksteps
    uint32_t qf[2][4][4];
#pragma unroll
    for (int ks = 0; ks < 4; ++ks) {
        ldsm4(qf[0][ks], lda_addr(sQ_u, wm*32,      ks*16, lane));
        ldsm4(qf[1][ks], lda_addr(sQ_u, wm*32 + 16, ks*16, lane));
    }

    const float SC = 0.18033688011112042f;   // log2(e)/8
    float rs[4] = {0.f, 0.f, 0.f, 0.f};      // rows: wm*32 + mi*16 + u*8 + lane/4

    for (int st = 0; st < 16; ++st) {
        int buf = st & 1;
        if (st + 1 < 16) { issueK(st + 1, buf ^ 1); CPA_WAIT1(); }
        else CPA_WAIT0();
        __syncthreads();
        uint32_t bK = sK_u + buf*16384;

        float acc[2][8][4];
#pragma unroll
        for (int mi = 0; mi < 2; ++mi)
#pragma unroll
            for (int ni = 0; ni < 8; ++ni)
#pragma unroll
                for (int c = 0; c < 4; ++c) acc[mi][ni][c] = 0.f;

#pragma unroll
        for (int ks = 0; ks < 4; ++ks) {
            uint32_t bfr[16];
#pragma unroll
            for (int j = 0; j < 4; ++j)
                ldsm4(&bfr[4*j], ldb_addr(bK, wn*64 + j*16, ks*16, lane));
#pragma unroll
            for (int mi = 0; mi < 2; ++mi)
#pragma unroll
                for (int ni = 0; ni < 8; ++ni)
                    mma_bf16(acc[mi][ni], qf[mi][ks], &bfr[ni*2]);
        }

        int s0 = st * 128;
        if (st == mt) {
            // diagonal tile: mask s == t
#pragma unroll
            for (int mi = 0; mi < 2; ++mi) {
                int r0 = t0 + wm*32 + mi*16 + (lane >> 2);
#pragma unroll
                for (int ni = 0; ni < 8; ++ni) {
                    int c0 = s0 + wn*64 + ni*8 + 2*(lane & 3);
                    float e0 = fex2(acc[mi][ni][0] * SC);
                    float e1 = fex2(acc[mi][ni][1] * SC);
                    float e2 = fex2(acc[mi][ni][2] * SC);
                    float e3 = fex2(acc[mi][ni][3] * SC);
                    rs[mi*2+0] += ((r0 == c0) ? 0.f : e0) + ((r0 == c0+1) ? 0.f : e1);
                    rs[mi*2+1] += ((r0+8 == c0) ? 0.f : e2) + ((r0+8 == c0+1) ? 0.f : e3);
                }
            }
        } else {
#pragma unroll
            for (int mi = 0; mi < 2; ++mi)
#pragma unroll
                for (int ni = 0; ni < 8; ++ni) {
                    float e0 = fex2(acc[mi][ni][0] * SC);
                    float e1 = fex2(acc[mi][ni][1] * SC);
                    float e2 = fex2(acc[mi][ni][2] * SC);
                    float e3 = fex2(acc[mi][ni][3] * SC);
                    rs[mi*2+0] += e0 + e1;
                    rs[mi*2+1] += e2 + e3;
                }
        }
        __syncthreads();
    }

    // Reduce: quad lanes (cols) -> warp-n halves -> log
#pragma unroll
    for (int i = 0; i < 4; ++i) {
        rs[i] += __shfl_xor_sync(0xffffffffu, rs[i], 1);
        rs[i] += __shfl_xor_sync(0xffffffffu, rs[i], 2);
    }
    if ((lane & 3) == 0) {
#pragma unroll
        for (int i = 0; i < 4; ++i) {
            int rl = wm*32 + (i >> 1)*16 + (i & 1)*8 + (lane >> 2);
            red[rl*2 + wn] = rs[i];
        }
    }
    __syncthreads();
    if (tid < 128) {
        float s = red[tid*2] + red[tid*2 + 1];
        out[(size_t)bh*NT + t0 + tid] = logf(s);
    }
}

// ---------------------------------------------------------------------------
extern "C" void kernel_launch(void* const* d_in, const int* in_sizes, int n_in,
                              void* d_out, int out_size) {
    const float* gq = (const float*)d_in[0];
    const float* gk = (const float*)d_in[1];
    const float* wq = (const float*)d_in[2];
    const float* wk = (const float*)d_in[3];
    float* out = (float*)d_out;

    __nv_bfloat16 *dGq, *dGk, *dWq, *dWk, *dQ, *dK;
    cudaGetSymbolAddress((void**)&dGq, g_Gq);
    cudaGetSymbolAddress((void**)&dGk, g_Gk);
    cudaGetSymbolAddress((void**)&dWq, g_Wq);
    cudaGetSymbolAddress((void**)&dWk, g_Wk);
    cudaGetSymbolAddress((void**)&dQ,  g_Q);
    cudaGetSymbolAddress((void**)&dK,  g_K);

    norm_kernel<<<NH, 256>>>(wq);
    int n4 = NB*NT*NE/4;
    conv_g_kernel<<<(n4+255)/256, 256>>>(gq, dGq, n4);
    conv_g_kernel<<<(n4+255)/256, 256>>>(gk, dGk, n4);
    conv_w_kernel<<<NH, 256>>>(wq, wk);

    static const int proj_smem = 2*16384 + 2*8192;            // 49152
    cudaFuncSetAttribute(proj_mma_kernel,
                         cudaFuncAttributeMaxDynamicSharedMemorySize, proj_smem);
    proj_mma_kernel<<<dim3(NT/128, NB*NH), 256, proj_smem>>>(dGq, dWq, dQ);
    proj_mma_kernel<<<dim3(NT/128, NB*NH), 256, proj_smem>>>(dGk, dWk, dK);

    static const int attn_smem = 16384 + 2*16384 + 256*4;     // 50176
    cudaFuncSetAttribute(attn_mma_kernel,
                         cudaFuncAttributeMaxDynamicSharedMemorySize, attn_smem);
    attn_mma_kernel<<<dim3(NT/128, NB*NH), 256, attn_smem>>>(out);
}